// round 1
// baseline (speedup 1.0000x reference)
#include <cuda_runtime.h>
#include <stdint.h>

#define NUM_SEQS 4
#define SEQ_LEN  4096
#define NTOK     (NUM_SEQS * SEQ_LEN)   // 16384
#define HIDDEN   2048
#define CONV_DIM 2048
#define KSZ      4
#define BCX_COLS (3 * CONV_DIM)         // 6144

// Scratch: static device globals (allocation-free per harness rules)
__device__ float g_bcx[(size_t)NTOK * BCX_COLS];   // ~402 MB
__device__ float g_y[(size_t)NTOK * CONV_DIM];     // ~134 MB

// ---------------------------------------------------------------------------
// SGEMM: C[M,N] = A[M,K] @ B[N,K]^T   (A,B,C row-major, all dims multiples of tile)
// BM=BN=128, BK=16, 256 threads, 8x8 micro-tile per thread.
// ---------------------------------------------------------------------------
#define BM 128
#define BN 128
#define BK 16
#define TM 8
#define TN 8

__global__ __launch_bounds__(256, 2)
void sgemm_abt(const float* __restrict__ A, const float* __restrict__ B,
               float* __restrict__ C, int M, int N, int K)
{
    __shared__ float As[BK * BM];
    __shared__ float Bs[BK * BN];

    const int tid = threadIdx.x;
    const int m0 = blockIdx.y * BM;
    const int n0 = blockIdx.x * BN;
    const int tx = tid % (BN / TN);   // 0..15 along N
    const int ty = tid / (BN / TN);   // 0..15 along M

    float acc[TM][TN];
#pragma unroll
    for (int i = 0; i < TM; i++)
#pragma unroll
        for (int j = 0; j < TN; j++) acc[i][j] = 0.0f;

    const float* Ab = A + (size_t)m0 * K;
    const float* Bb = B + (size_t)n0 * K;

    for (int k0 = 0; k0 < K; k0 += BK) {
        // Load 128x16 A-tile and B-tile, transposed into SMEM [k][row]
#pragma unroll
        for (int i = 0; i < 2; i++) {
            int lin = tid + i * 256;        // 0..511
            int row = lin >> 2;             // 0..127
            int kc  = (lin & 3) << 2;       // 0,4,8,12
            float4 va = *(const float4*)(Ab + (size_t)row * K + k0 + kc);
            As[(kc + 0) * BM + row] = va.x;
            As[(kc + 1) * BM + row] = va.y;
            As[(kc + 2) * BM + row] = va.z;
            As[(kc + 3) * BM + row] = va.w;
            float4 vb = *(const float4*)(Bb + (size_t)row * K + k0 + kc);
            Bs[(kc + 0) * BN + row] = vb.x;
            Bs[(kc + 1) * BN + row] = vb.y;
            Bs[(kc + 2) * BN + row] = vb.z;
            Bs[(kc + 3) * BN + row] = vb.w;
        }
        __syncthreads();

#pragma unroll
        for (int kk = 0; kk < BK; kk++) {
            float a[TM], b[TN];
            float4 a0 = *(const float4*)&As[kk * BM + ty * TM];
            float4 a1 = *(const float4*)&As[kk * BM + ty * TM + 4];
            float4 b0 = *(const float4*)&Bs[kk * BN + tx * TN];
            float4 b1 = *(const float4*)&Bs[kk * BN + tx * TN + 4];
            a[0] = a0.x; a[1] = a0.y; a[2] = a0.z; a[3] = a0.w;
            a[4] = a1.x; a[5] = a1.y; a[6] = a1.z; a[7] = a1.w;
            b[0] = b0.x; b[1] = b0.y; b[2] = b0.z; b[3] = b0.w;
            b[4] = b1.x; b[5] = b1.y; b[6] = b1.z; b[7] = b1.w;
#pragma unroll
            for (int i = 0; i < TM; i++)
#pragma unroll
                for (int j = 0; j < TN; j++)
                    acc[i][j] = fmaf(a[i], b[j], acc[i][j]);
        }
        __syncthreads();
    }

    // Epilogue: vectorized store
#pragma unroll
    for (int i = 0; i < TM; i++) {
        float* Crow = C + (size_t)(m0 + ty * TM + i) * N + n0 + tx * TN;
        float4 v0 = make_float4(acc[i][0], acc[i][1], acc[i][2], acc[i][3]);
        float4 v1 = make_float4(acc[i][4], acc[i][5], acc[i][6], acc[i][7]);
        *(float4*)(Crow)     = v0;
        *(float4*)(Crow + 4) = v1;
    }
}

// ---------------------------------------------------------------------------
// Gate + causal depthwise conv + BCx gate + final conv-state extraction.
// conv_out[t,d] = sum_{j=0..3} w[d,j] * bx[t-3+j]   (zero left pad per sequence)
// y[t,d] = c[t,d] * conv_out[t,d];  states[s, r, d] = bx[seq_end-3+r, d]
// Each thread handles 8 consecutive tokens for one channel (rolling window).
// ---------------------------------------------------------------------------
#define TPER 8

__device__ __forceinline__ float bx_at(int t, int d) {
    const float* p = &g_bcx[(size_t)t * BCX_COLS];
    return p[d] * p[2 * CONV_DIM + d];
}

__global__ __launch_bounds__(256)
void conv_gate_kernel(const float* __restrict__ cw, float* __restrict__ states_out)
{
    int d  = blockIdx.x * blockDim.x + threadIdx.x;  // channel 0..2047
    int t0 = blockIdx.y * TPER;                      // strip start (never crosses seq boundary)
    int pos0 = t0 & (SEQ_LEN - 1);

    float w0 = cw[d * KSZ + 0];
    float w1 = cw[d * KSZ + 1];
    float w2 = cw[d * KSZ + 2];
    float w3 = cw[d * KSZ + 3];

    float h0 = 0.f, h1 = 0.f, h2 = 0.f;  // bx[t-3], bx[t-2], bx[t-1]
    if (pos0 >= 3) h0 = bx_at(t0 - 3, d);
    if (pos0 >= 2) h1 = bx_at(t0 - 2, d);
    if (pos0 >= 1) h2 = bx_at(t0 - 1, d);

#pragma unroll
    for (int i = 0; i < TPER; i++) {
        int t = t0 + i;
        float bx = bx_at(t, d);
        float conv = fmaf(w0, h0, fmaf(w1, h1, fmaf(w2, h2, w3 * bx)));
        float c = g_bcx[(size_t)t * BCX_COLS + CONV_DIM + d];
        g_y[(size_t)t * CONV_DIM + d] = c * conv;

        int pos = pos0 + i;
        if (pos >= SEQ_LEN - (KSZ - 1)) {
            int seq = t >> 12;  // / SEQ_LEN
            int r   = pos - (SEQ_LEN - (KSZ - 1));
            states_out[((size_t)seq * (KSZ - 1) + r) * CONV_DIM + d] = bx;
        }
        h0 = h1; h1 = h2; h2 = bx;
    }
}

// ---------------------------------------------------------------------------
// Launch
// ---------------------------------------------------------------------------
extern "C" void kernel_launch(void* const* d_in, const int* in_sizes, int n_in,
                              void* d_out, int out_size)
{
    const float* hidden = (const float*)d_in[0];  // [16384, 2048]
    const float* w_in   = (const float*)d_in[1];  // [6144, 2048]
    const float* convw  = (const float*)d_in[2];  // [2048, 4]
    const float* w_out  = (const float*)d_in[3];  // [2048, 2048]
    float* out = (float*)d_out;                   // [16384*2048] then [4*3*2048]

    float* bcx = nullptr;
    float* y   = nullptr;
    cudaGetSymbolAddress((void**)&bcx, g_bcx);
    cudaGetSymbolAddress((void**)&y,   g_y);

    // 1) bcx = hidden @ w_in^T   [16384 x 6144]
    {
        dim3 grid(BCX_COLS / BN, NTOK / BM);
        sgemm_abt<<<grid, 256>>>(hidden, w_in, bcx, NTOK, BCX_COLS, HIDDEN);
    }

    // 2) gate + conv + BCx gate + states
    {
        dim3 grid(CONV_DIM / 256, NTOK / TPER);
        conv_gate_kernel<<<grid, 256>>>(convw, out + (size_t)NTOK * HIDDEN);
    }

    // 3) out = y @ w_out^T   [16384 x 2048]
    {
        dim3 grid(HIDDEN / BN, NTOK / BM);
        sgemm_abt<<<grid, 256>>>(y, w_out, out, NTOK, HIDDEN, CONV_DIM);
    }
}

// round 3
// speedup vs baseline: 2.3525x; 2.3525x over previous
#include <cuda_runtime.h>
#include <cuda_bf16.h>
#include <stdint.h>

#define NUM_SEQS 4
#define SEQ_LEN  4096
#define NTOK     16384
#define HIDDEN   2048
#define CONV_DIM 2048
#define KSZ      4
#define BCX_COLS 6144
#define KDIM     2048

// ---------------- scratch (static device globals; allocation-free) ----------
__device__ float g_bcx[(size_t)NTOK * BCX_COLS];                 // 402 MB
__device__ __nv_bfloat16 g_ah[(size_t)NTOK * KDIM];
__device__ __nv_bfloat16 g_al[(size_t)NTOK * KDIM];
__device__ __nv_bfloat16 g_winh[(size_t)BCX_COLS * KDIM];
__device__ __nv_bfloat16 g_winl[(size_t)BCX_COLS * KDIM];
__device__ __nv_bfloat16 g_wouth[(size_t)HIDDEN * KDIM];
__device__ __nv_bfloat16 g_woutl[(size_t)HIDDEN * KDIM];
__device__ __nv_bfloat16 g_yh[(size_t)NTOK * KDIM];
__device__ __nv_bfloat16 g_yl[(size_t)NTOK * KDIM];

// ---------------- ptx helpers (baseline ISA only; no 'a' features) ----------
__device__ __forceinline__ uint32_t smem_u32(const void* p) {
    uint32_t a;
    asm("{ .reg .u64 t; cvta.to.shared.u64 t, %1; cvt.u32.u64 %0, t; }" : "=r"(a) : "l"(p));
    return a;
}
__device__ __forceinline__ void cpasync16(uint32_t dst, const void* src) {
    asm volatile("cp.async.cg.shared.global [%0], [%1], 16;" :: "r"(dst), "l"(src));
}
__device__ __forceinline__ void cp_commit() { asm volatile("cp.async.commit_group;" ::: "memory"); }

#define LDSM4(r, addr)                                                      \
    asm volatile("ldmatrix.sync.aligned.m8n8.x4.shared.b16 {%0,%1,%2,%3}, [%4];" \
        : "=r"((r)[0]), "=r"((r)[1]), "=r"((r)[2]), "=r"((r)[3]) : "r"(addr))

#define MMA16816(acc, a, b0r, b1r)                                          \
    asm volatile("mma.sync.aligned.m16n8k16.row.col.f32.bf16.bf16.f32 "     \
        "{%0,%1,%2,%3}, {%4,%5,%6,%7}, {%8,%9}, {%0,%1,%2,%3};"             \
        : "+f"((acc)[0]), "+f"((acc)[1]), "+f"((acc)[2]), "+f"((acc)[3])    \
        : "r"((a)[0]), "r"((a)[1]), "r"((a)[2]), "r"((a)[3]),               \
          "r"(b0r), "r"(b1r))

// ---------------- bf16x3 GEMM: C[M,N] = (Ah+Al)[M,K] @ (Bh+Bl)[N,K]^T ------
// CTA tile 128x128, BK=32, 4-stage cp.async ring, 8 warps (warp tile 64x32)
#define BM 128
#define BN 128
#define BKC 32
#define NC (KDIM / BKC)              // 64 chunks
#define STAGE_BYTES 32768            // Ah 8K | Al 8K | Bh 8K | Bl 8K
#define NSTAGE 4
#define GSMEM_TOTAL (NSTAGE * STAGE_BYTES)   // 128 KB

// swizzle of the (r*32 + h*16) intra-matrix offset: XOR bit7(row bit2) into bit4
__device__ __forceinline__ uint32_t swz(uint32_t off) {
    return off ^ ((off >> 3) & 0x10);
}

__global__ __launch_bounds__(256, 1)
void gemm_bf16x3(const __nv_bfloat16* __restrict__ Ah, const __nv_bfloat16* __restrict__ Al,
                 const __nv_bfloat16* __restrict__ Bh, const __nv_bfloat16* __restrict__ Bl,
                 float* __restrict__ C, int ldC)
{
    extern __shared__ char smem[];
    const uint32_t sbase = smem_u32(smem);
    const int tid  = threadIdx.x;
    const int lane = tid & 31;
    const int wid  = tid >> 5;
    const int wm   = wid >> 2;       // 0..1 (M dim, 64 rows each)
    const int wn   = wid & 3;        // 0..3 (N dim, 32 cols each)
    const int m0 = blockIdx.y * BM;
    const int n0 = blockIdx.x * BN;

    // global row bases per sub-matrix (A rows from m0, B rows from n0)
    const __nv_bfloat16* gbase[4];
    gbase[0] = Ah + (size_t)m0 * KDIM;
    gbase[1] = Al + (size_t)m0 * KDIM;
    gbase[2] = Bh + (size_t)n0 * KDIM;
    gbase[3] = Bl + (size_t)n0 * KDIM;

    // per-thread cp.async decode (8 chunks of 16B per thread per stage-fill)
    // idx = p*256+tid in [0,2048): mat(2b) | r(7b) | q(1b) | h(1b)
    // smem: mat*8192 + q*4096 + swz(r*32 + h*16)

    // ldmatrix lane addresses (within one [128][32B] sub-matrix, before q*4096)
    uint32_t swA[4];
#pragma unroll
    for (int mt = 0; mt < 4; mt++) {
        uint32_t r = wm * 64 + mt * 16 + (lane & 15);
        uint32_t off = r * 32 + (lane >> 4) * 16;
        swA[mt] = swz(off);
    }
    uint32_t swB[2];
#pragma unroll
    for (int p = 0; p < 2; p++) {
        uint32_t r = wn * 32 + p * 16 + (lane & 7) + ((lane >> 4) << 3);
        uint32_t off = r * 32 + ((lane >> 3) & 1) * 16;
        swB[p] = swz(off);
    }

    float acc[4][4][4];
#pragma unroll
    for (int i = 0; i < 4; i++)
#pragma unroll
        for (int j = 0; j < 4; j++)
#pragma unroll
            for (int q = 0; q < 4; q++) acc[i][j][q] = 0.0f;

    // ---- stage filler ----
    auto load_chunk = [&](int c, int st) {
        uint32_t stg = sbase + st * STAGE_BYTES;
#pragma unroll
        for (int p = 0; p < 8; p++) {
            int idx = p * 256 + tid;
            int mat = idx >> 9;
            int rem = idx & 511;
            int r = rem >> 2, q = (rem >> 1) & 1, h = rem & 1;
            uint32_t dst = stg + mat * 8192 + q * 4096 + swz((uint32_t)(r * 32 + h * 16));
            cpasync16(dst, gbase[mat] + (size_t)r * KDIM + c * BKC + q * 16 + h * 8);
        }
    };

    // prologue: stages 0,1,2
    load_chunk(0, 0); cp_commit();
    load_chunk(1, 1); cp_commit();
    load_chunk(2, 2); cp_commit();
    asm volatile("cp.async.wait_group 2;" ::: "memory");
    __syncthreads();

    for (int ch = 0; ch < NC; ch++) {
        const uint32_t stg = sbase + (ch & 3) * STAGE_BYTES;
#pragma unroll
        for (int q = 0; q < 2; q++) {
            const uint32_t qb = stg + q * 4096;
            uint32_t ah[4][4], al[4][4], bh[2][4], bl[2][4];
#pragma unroll
            for (int mt = 0; mt < 4; mt++) {
                LDSM4(ah[mt], qb + swA[mt]);
                LDSM4(al[mt], qb + 8192 + swA[mt]);
            }
#pragma unroll
            for (int p = 0; p < 2; p++) {
                LDSM4(bh[p], qb + 16384 + swB[p]);
                LDSM4(bl[p], qb + 24576 + swB[p]);
            }
#pragma unroll
            for (int mt = 0; mt < 4; mt++) {
#pragma unroll
                for (int nt = 0; nt < 4; nt++) {
                    const uint32_t* bhp = bh[nt >> 1];
                    const uint32_t* blp = bl[nt >> 1];
                    int bi = (nt & 1) * 2;
                    MMA16816(acc[mt][nt], ah[mt], bhp[bi], bhp[bi + 1]);
                    MMA16816(acc[mt][nt], ah[mt], blp[bi], blp[bi + 1]);
                    MMA16816(acc[mt][nt], al[mt], bhp[bi], bhp[bi + 1]);
                }
            }
        }
        __syncthreads();
        if (ch + 3 < NC) load_chunk(ch + 3, (ch + 3) & 3);
        cp_commit();   // empty groups at tail keep the group count uniform
        asm volatile("cp.async.wait_group 2;" ::: "memory");
        __syncthreads();
    }

    // epilogue: direct fp32 stores (float2, 32B-sector aligned per quad)
    const int rw = m0 + wm * 64 + (lane >> 2);
    const int cw = n0 + wn * 32 + (lane & 3) * 2;
#pragma unroll
    for (int mt = 0; mt < 4; mt++) {
#pragma unroll
        for (int nt = 0; nt < 4; nt++) {
            float* p0 = C + (size_t)(rw + mt * 16) * ldC + cw + nt * 8;
            float* p1 = C + (size_t)(rw + mt * 16 + 8) * ldC + cw + nt * 8;
            *(float2*)p0 = make_float2(acc[mt][nt][0], acc[mt][nt][1]);
            *(float2*)p1 = make_float2(acc[mt][nt][2], acc[mt][nt][3]);
        }
    }
}

// ---------------- fp32 -> bf16 hi/lo split ----------------------------------
__global__ __launch_bounds__(256)
void split_kernel(const float* __restrict__ in, __nv_bfloat16* __restrict__ hi,
                  __nv_bfloat16* __restrict__ lo, int n4)
{
    int i = blockIdx.x * blockDim.x + threadIdx.x;
    if (i >= n4) return;
    float4 v = ((const float4*)in)[i];
    __nv_bfloat16 h0 = __float2bfloat16(v.x), h1 = __float2bfloat16(v.y);
    __nv_bfloat16 h2 = __float2bfloat16(v.z), h3 = __float2bfloat16(v.w);
    __nv_bfloat16 l0 = __float2bfloat16(v.x - __bfloat162float(h0));
    __nv_bfloat16 l1 = __float2bfloat16(v.y - __bfloat162float(h1));
    __nv_bfloat16 l2 = __float2bfloat16(v.z - __bfloat162float(h2));
    __nv_bfloat16 l3 = __float2bfloat16(v.w - __bfloat162float(h3));
    ((__nv_bfloat162*)hi)[i * 2 + 0] = __nv_bfloat162(h0, h1);
    ((__nv_bfloat162*)hi)[i * 2 + 1] = __nv_bfloat162(h2, h3);
    ((__nv_bfloat162*)lo)[i * 2 + 0] = __nv_bfloat162(l0, l1);
    ((__nv_bfloat162*)lo)[i * 2 + 1] = __nv_bfloat162(l2, l3);
}

// ---------------- gate + causal conv + BCx gate + states; y -> bf16 hi/lo ---
#define TPER 8
__device__ __forceinline__ float bx_at(int t, int d) {
    const float* p = &g_bcx[(size_t)t * BCX_COLS];
    return p[d] * p[2 * CONV_DIM + d];
}

__global__ __launch_bounds__(256)
void conv_gate_kernel(const float* __restrict__ cw, float* __restrict__ states_out)
{
    int d  = blockIdx.x * blockDim.x + threadIdx.x;
    int t0 = blockIdx.y * TPER;
    int pos0 = t0 & (SEQ_LEN - 1);

    float w0 = cw[d * KSZ + 0];
    float w1 = cw[d * KSZ + 1];
    float w2 = cw[d * KSZ + 2];
    float w3 = cw[d * KSZ + 3];

    float h0 = 0.f, h1 = 0.f, h2 = 0.f;
    if (pos0 >= 3) h0 = bx_at(t0 - 3, d);
    if (pos0 >= 2) h1 = bx_at(t0 - 2, d);
    if (pos0 >= 1) h2 = bx_at(t0 - 1, d);

#pragma unroll
    for (int i = 0; i < TPER; i++) {
        int t = t0 + i;
        float bx = bx_at(t, d);
        float conv = fmaf(w0, h0, fmaf(w1, h1, fmaf(w2, h2, w3 * bx)));
        float c = g_bcx[(size_t)t * BCX_COLS + CONV_DIM + d];
        float yv = c * conv;
        size_t yi = (size_t)t * CONV_DIM + d;
        __nv_bfloat16 yh = __float2bfloat16(yv);
        g_yh[yi] = yh;
        g_yl[yi] = __float2bfloat16(yv - __bfloat162float(yh));

        int pos = pos0 + i;
        if (pos >= SEQ_LEN - (KSZ - 1)) {
            int seq = t >> 12;
            int r   = pos - (SEQ_LEN - (KSZ - 1));
            states_out[((size_t)seq * (KSZ - 1) + r) * CONV_DIM + d] = bx;
        }
        h0 = h1; h1 = h2; h2 = bx;
    }
}

// ---------------- launch -----------------------------------------------------
extern "C" void kernel_launch(void* const* d_in, const int* in_sizes, int n_in,
                              void* d_out, int out_size)
{
    const float* hidden = (const float*)d_in[0];  // [16384, 2048]
    const float* w_in   = (const float*)d_in[1];  // [6144, 2048]
    const float* convw  = (const float*)d_in[2];  // [2048, 4]
    const float* w_out  = (const float*)d_in[3];  // [2048, 2048]
    float* out = (float*)d_out;

    float* bcx; __nv_bfloat16 *ah, *al, *winh, *winl, *wouth, *woutl, *yh, *yl;
    cudaGetSymbolAddress((void**)&bcx,   g_bcx);
    cudaGetSymbolAddress((void**)&ah,    g_ah);
    cudaGetSymbolAddress((void**)&al,    g_al);
    cudaGetSymbolAddress((void**)&winh,  g_winh);
    cudaGetSymbolAddress((void**)&winl,  g_winl);
    cudaGetSymbolAddress((void**)&wouth, g_wouth);
    cudaGetSymbolAddress((void**)&woutl, g_woutl);
    cudaGetSymbolAddress((void**)&yh,    g_yh);
    cudaGetSymbolAddress((void**)&yl,    g_yl);

    cudaFuncSetAttribute(gemm_bf16x3, cudaFuncAttributeMaxDynamicSharedMemorySize, GSMEM_TOTAL);

    // splits
    {
        int n4 = NTOK * KDIM / 4;
        split_kernel<<<n4 / 256, 256>>>(hidden, ah, al, n4);
        n4 = BCX_COLS * KDIM / 4;
        split_kernel<<<n4 / 256, 256>>>(w_in, winh, winl, n4);
        n4 = HIDDEN * KDIM / 4;
        split_kernel<<<n4 / 256, 256>>>(w_out, wouth, woutl, n4);
    }

    // GEMM1: bcx = hidden @ w_in^T  [16384 x 6144]
    gemm_bf16x3<<<dim3(BCX_COLS / BN, NTOK / BM), 256, GSMEM_TOTAL>>>(ah, al, winh, winl, bcx, BCX_COLS);

    // conv + gates + states (+ y split)
    conv_gate_kernel<<<dim3(CONV_DIM / 256, NTOK / TPER), 256>>>(convw, out + (size_t)NTOK * HIDDEN);

    // GEMM2: out = y @ w_out^T  [16384 x 2048]
    gemm_bf16x3<<<dim3(HIDDEN / BN, NTOK / BM), 256, GSMEM_TOTAL>>>(yh, yl, wouth, woutl, out, HIDDEN);
}

// round 4
// speedup vs baseline: 3.4668x; 1.4736x over previous
#include <cuda_runtime.h>
#include <cuda_bf16.h>
#include <stdint.h>

#define NUM_SEQS 4
#define SEQ_LEN  4096
#define NTOK     16384
#define HIDDEN   2048
#define CONV_DIM 2048
#define KSZ      4
#define BCX_COLS 6144
#define KDIM     2048

// ---------------- scratch (static device globals; allocation-free) ----------
__device__ float g_bcx[(size_t)NTOK * BCX_COLS];
__device__ __nv_bfloat16 g_ah[(size_t)NTOK * KDIM];
__device__ __nv_bfloat16 g_al[(size_t)NTOK * KDIM];
__device__ __nv_bfloat16 g_winh[(size_t)BCX_COLS * KDIM];
__device__ __nv_bfloat16 g_winl[(size_t)BCX_COLS * KDIM];
__device__ __nv_bfloat16 g_wouth[(size_t)HIDDEN * KDIM];
__device__ __nv_bfloat16 g_woutl[(size_t)HIDDEN * KDIM];
__device__ __nv_bfloat16 g_yh[(size_t)NTOK * KDIM];
__device__ __nv_bfloat16 g_yl[(size_t)NTOK * KDIM];

// ---------------- ptx helpers (baseline ISA only) ----------------------------
__device__ __forceinline__ uint32_t smem_u32(const void* p) {
    uint32_t a;
    asm("{ .reg .u64 t; cvta.to.shared.u64 t, %1; cvt.u32.u64 %0, t; }" : "=r"(a) : "l"(p));
    return a;
}
__device__ __forceinline__ void cpasync16(uint32_t dst, const void* src) {
    asm volatile("cp.async.cg.shared.global [%0], [%1], 16;" :: "r"(dst), "l"(src));
}
__device__ __forceinline__ void cp_commit() { asm volatile("cp.async.commit_group;" ::: "memory"); }
__device__ __forceinline__ void cp_wait0()  { asm volatile("cp.async.wait_group 0;" ::: "memory"); }

#define LDSM4(r, addr)                                                      \
    asm volatile("ldmatrix.sync.aligned.m8n8.x4.shared.b16 {%0,%1,%2,%3}, [%4];" \
        : "=r"((r)[0]), "=r"((r)[1]), "=r"((r)[2]), "=r"((r)[3]) : "r"(addr))

#define MMA16816(acc, a, b0r, b1r)                                          \
    asm volatile("mma.sync.aligned.m16n8k16.row.col.f32.bf16.bf16.f32 "     \
        "{%0,%1,%2,%3}, {%4,%5,%6,%7}, {%8,%9}, {%0,%1,%2,%3};"             \
        : "+f"((acc)[0]), "+f"((acc)[1]), "+f"((acc)[2]), "+f"((acc)[3])    \
        : "r"((a)[0]), "r"((a)[1]), "r"((a)[2]), "r"((a)[3]),               \
          "r"(b0r), "r"(b1r))

// SW128 swizzle on 128B rows
__device__ __forceinline__ uint32_t swz128(uint32_t off) { return off ^ ((off >> 3) & 0x70); }

// ---------------- bf16x3 GEMM: C[M,N] = (Ah+Al)[M,K] @ (Bh+Bl)[N,K]^T -------
// CTA 128x256, 8 warps (2x4), warp tile 64x64, BK=64, 2-stage, 1 barrier/iter
#define BM 128
#define BN 256
#define BKC 64
#define NC (KDIM / BKC)              // 32
// stage layout: Ah 16K | Al 16K | Bh 32K | Bl 32K = 96KB
#define OFF_AH 0
#define OFF_AL 16384
#define OFF_BH 32768
#define OFF_BL 65536
#define STAGE_BYTES 98304
#define GSMEM_TOTAL (2 * STAGE_BYTES)   // 192KB

__global__ __launch_bounds__(256, 1)
void gemm_bf16x3(const __nv_bfloat16* __restrict__ Ah, const __nv_bfloat16* __restrict__ Al,
                 const __nv_bfloat16* __restrict__ Bh, const __nv_bfloat16* __restrict__ Bl,
                 float* __restrict__ C, int ldC)
{
    extern __shared__ char smem[];
    const uint32_t sbase = smem_u32(smem);
    const int tid  = threadIdx.x;
    const int lane = tid & 31;
    const int wid  = tid >> 5;
    const int wm   = wid >> 2;       // 0..1  (64 rows each)
    const int wn   = wid & 3;        // 0..3  (64 cols each)
    const int m0 = blockIdx.y * BM;
    const int n0 = blockIdx.x * BN;

    const __nv_bfloat16* gA[2] = { Ah + (size_t)m0 * KDIM, Al + (size_t)m0 * KDIM };
    const __nv_bfloat16* gB[2] = { Bh + (size_t)n0 * KDIM, Bl + (size_t)n0 * KDIM };

    // ldmatrix lane address components (within one sub-matrix, before stage base)
    // A: row = wm*64 + mt*16 + (lane&15), kb = q*2 + (lane>>4)
    uint32_t aRow[4], aXor[4];
#pragma unroll
    for (int mt = 0; mt < 4; mt++) {
        uint32_t r = wm * 64 + mt * 16 + (lane & 15);
        aRow[mt] = r * 128;
        aXor[mt] = (aRow[mt] >> 3) & 0x70;
    }
    const uint32_t aKb = (lane >> 4);            // +q*2
    // B: row = wn*64 + p*16 + (lane&7) + ((lane>>4)<<3), kb = q*2 + ((lane>>3)&1)
    uint32_t bRow[4], bXor[4];
#pragma unroll
    for (int p = 0; p < 4; p++) {
        uint32_t r = wn * 64 + p * 16 + (lane & 7) + ((lane >> 4) << 3);
        bRow[p] = r * 128;
        bXor[p] = (bRow[p] >> 3) & 0x70;
    }
    const uint32_t bKb = ((lane >> 3) & 1);      // +q*2

    float acc[4][8][4];
#pragma unroll
    for (int i = 0; i < 4; i++)
#pragma unroll
        for (int j = 0; j < 8; j++)
#pragma unroll
            for (int q = 0; q < 4; q++) acc[i][j][q] = 0.0f;

    // stage filler: 24 x 16B per thread (Ah/Al: 1024 units each; Bh/Bl: 2048 each)
    auto load_chunk = [&](int c, int st) {
        const uint32_t stg = sbase + st * STAGE_BYTES;
        const int koff = c * BKC;
#pragma unroll
        for (int p = 0; p < 4; p++) {            // Ah
            int rem = p * 256 + tid;
            int r = rem >> 3, kb = rem & 7;
            cpasync16(stg + OFF_AH + swz128(r * 128 + kb * 16),
                      gA[0] + (size_t)r * KDIM + koff + kb * 8);
        }
#pragma unroll
        for (int p = 0; p < 4; p++) {            // Al
            int rem = p * 256 + tid;
            int r = rem >> 3, kb = rem & 7;
            cpasync16(stg + OFF_AL + swz128(r * 128 + kb * 16),
                      gA[1] + (size_t)r * KDIM + koff + kb * 8);
        }
#pragma unroll
        for (int p = 0; p < 8; p++) {            // Bh
            int rem = p * 256 + tid;
            int r = rem >> 3, kb = rem & 7;
            cpasync16(stg + OFF_BH + swz128(r * 128 + kb * 16),
                      gB[0] + (size_t)r * KDIM + koff + kb * 8);
        }
#pragma unroll
        for (int p = 0; p < 8; p++) {            // Bl
            int rem = p * 256 + tid;
            int r = rem >> 3, kb = rem & 7;
            cpasync16(stg + OFF_BL + swz128(r * 128 + kb * 16),
                      gB[1] + (size_t)r * KDIM + koff + kb * 8);
        }
    };

    // prologue
    load_chunk(0, 0);
    cp_commit();
    cp_wait0();
    __syncthreads();

    for (int ch = 0; ch < NC; ch++) {
        // issue next chunk first (overlaps with this chunk's MMAs)
        if (ch + 1 < NC) load_chunk(ch + 1, (ch + 1) & 1);
        cp_commit();

        const uint32_t stg = sbase + (ch & 1) * STAGE_BYTES;
#pragma unroll
        for (int q = 0; q < 4; q++) {
            const uint32_t kb_a = (q * 2 + aKb) * 16;
            const uint32_t kb_b = (q * 2 + bKb) * 16;
            uint32_t ah[4][4], al[4][4], bh[4][4], bl[4][4];
#pragma unroll
            for (int mt = 0; mt < 4; mt++) {
                uint32_t ad = stg + aRow[mt] + (kb_a ^ aXor[mt]);
                LDSM4(ah[mt], ad + OFF_AH);
                LDSM4(al[mt], ad + OFF_AL);
            }
#pragma unroll
            for (int p = 0; p < 4; p++) {
                uint32_t bd = stg + bRow[p] + (kb_b ^ bXor[p]);
                LDSM4(bh[p], bd + OFF_BH);
                LDSM4(bl[p], bd + OFF_BL);
            }
#pragma unroll
            for (int mt = 0; mt < 4; mt++) {
#pragma unroll
                for (int nt = 0; nt < 8; nt++) {
                    const int p = nt >> 1, bi = (nt & 1) * 2;
                    MMA16816(acc[mt][nt], ah[mt], bh[p][bi], bh[p][bi + 1]);
                    MMA16816(acc[mt][nt], ah[mt], bl[p][bi], bl[p][bi + 1]);
                    MMA16816(acc[mt][nt], al[mt], bh[p][bi], bh[p][bi + 1]);
                }
            }
        }
        cp_wait0();
        __syncthreads();
    }

    // epilogue
    const int rw = m0 + wm * 64 + (lane >> 2);
    const int cw = n0 + wn * 64 + (lane & 3) * 2;
#pragma unroll
    for (int mt = 0; mt < 4; mt++) {
#pragma unroll
        for (int nt = 0; nt < 8; nt++) {
            float* p0 = C + (size_t)(rw + mt * 16) * ldC + cw + nt * 8;
            float* p1 = C + (size_t)(rw + mt * 16 + 8) * ldC + cw + nt * 8;
            *(float2*)p0 = make_float2(acc[mt][nt][0], acc[mt][nt][1]);
            *(float2*)p1 = make_float2(acc[mt][nt][2], acc[mt][nt][3]);
        }
    }
}

// ---------------- fp32 -> bf16 hi/lo split ----------------------------------
__global__ __launch_bounds__(256)
void split_kernel(const float* __restrict__ in, __nv_bfloat16* __restrict__ hi,
                  __nv_bfloat16* __restrict__ lo, int n4)
{
    int i = blockIdx.x * blockDim.x + threadIdx.x;
    if (i >= n4) return;
    float4 v = ((const float4*)in)[i];
    __nv_bfloat16 h0 = __float2bfloat16(v.x), h1 = __float2bfloat16(v.y);
    __nv_bfloat16 h2 = __float2bfloat16(v.z), h3 = __float2bfloat16(v.w);
    __nv_bfloat16 l0 = __float2bfloat16(v.x - __bfloat162float(h0));
    __nv_bfloat16 l1 = __float2bfloat16(v.y - __bfloat162float(h1));
    __nv_bfloat16 l2 = __float2bfloat16(v.z - __bfloat162float(h2));
    __nv_bfloat16 l3 = __float2bfloat16(v.w - __bfloat162float(h3));
    ((__nv_bfloat162*)hi)[i * 2 + 0] = __nv_bfloat162(h0, h1);
    ((__nv_bfloat162*)hi)[i * 2 + 1] = __nv_bfloat162(h2, h3);
    ((__nv_bfloat162*)lo)[i * 2 + 0] = __nv_bfloat162(l0, l1);
    ((__nv_bfloat162*)lo)[i * 2 + 1] = __nv_bfloat162(l2, l3);
}

// ---------------- gate + causal conv + BCx gate + states; y -> bf16 hi/lo ---
#define TPER 8
__device__ __forceinline__ float bx_at(int t, int d) {
    const float* p = &g_bcx[(size_t)t * BCX_COLS];
    return p[d] * p[2 * CONV_DIM + d];
}

__global__ __launch_bounds__(256)
void conv_gate_kernel(const float* __restrict__ cw, float* __restrict__ states_out)
{
    int d  = blockIdx.x * blockDim.x + threadIdx.x;
    int t0 = blockIdx.y * TPER;
    int pos0 = t0 & (SEQ_LEN - 1);

    float w0 = cw[d * KSZ + 0];
    float w1 = cw[d * KSZ + 1];
    float w2 = cw[d * KSZ + 2];
    float w3 = cw[d * KSZ + 3];

    float h0 = 0.f, h1 = 0.f, h2 = 0.f;
    if (pos0 >= 3) h0 = bx_at(t0 - 3, d);
    if (pos0 >= 2) h1 = bx_at(t0 - 2, d);
    if (pos0 >= 1) h2 = bx_at(t0 - 1, d);

#pragma unroll
    for (int i = 0; i < TPER; i++) {
        int t = t0 + i;
        float bx = bx_at(t, d);
        float conv = fmaf(w0, h0, fmaf(w1, h1, fmaf(w2, h2, w3 * bx)));
        float c = g_bcx[(size_t)t * BCX_COLS + CONV_DIM + d];
        float yv = c * conv;
        size_t yi = (size_t)t * CONV_DIM + d;
        __nv_bfloat16 yh = __float2bfloat16(yv);
        g_yh[yi] = yh;
        g_yl[yi] = __float2bfloat16(yv - __bfloat162float(yh));

        int pos = pos0 + i;
        if (pos >= SEQ_LEN - (KSZ - 1)) {
            int seq = t >> 12;
            int r   = pos - (SEQ_LEN - (KSZ - 1));
            states_out[((size_t)seq * (KSZ - 1) + r) * CONV_DIM + d] = bx;
        }
        h0 = h1; h1 = h2; h2 = bx;
    }
}

// ---------------- launch -----------------------------------------------------
extern "C" void kernel_launch(void* const* d_in, const int* in_sizes, int n_in,
                              void* d_out, int out_size)
{
    const float* hidden = (const float*)d_in[0];
    const float* w_in   = (const float*)d_in[1];
    const float* convw  = (const float*)d_in[2];
    const float* w_out  = (const float*)d_in[3];
    float* out = (float*)d_out;

    float* bcx; __nv_bfloat16 *ah, *al, *winh, *winl, *wouth, *woutl, *yh, *yl;
    cudaGetSymbolAddress((void**)&bcx,   g_bcx);
    cudaGetSymbolAddress((void**)&ah,    g_ah);
    cudaGetSymbolAddress((void**)&al,    g_al);
    cudaGetSymbolAddress((void**)&winh,  g_winh);
    cudaGetSymbolAddress((void**)&winl,  g_winl);
    cudaGetSymbolAddress((void**)&wouth, g_wouth);
    cudaGetSymbolAddress((void**)&woutl, g_woutl);
    cudaGetSymbolAddress((void**)&yh,    g_yh);
    cudaGetSymbolAddress((void**)&yl,    g_yl);

    cudaFuncSetAttribute(gemm_bf16x3, cudaFuncAttributeMaxDynamicSharedMemorySize, GSMEM_TOTAL);

    // splits
    {
        int n4 = NTOK * KDIM / 4;
        split_kernel<<<n4 / 256, 256>>>(hidden, ah, al, n4);
        n4 = BCX_COLS * KDIM / 4;
        split_kernel<<<n4 / 256, 256>>>(w_in, winh, winl, n4);
        n4 = HIDDEN * KDIM / 4;
        split_kernel<<<n4 / 256, 256>>>(w_out, wouth, woutl, n4);
    }

    // GEMM1: bcx = hidden @ w_in^T  [16384 x 6144]
    gemm_bf16x3<<<dim3(BCX_COLS / BN, NTOK / BM), 256, GSMEM_TOTAL>>>(ah, al, winh, winl, bcx, BCX_COLS);

    // conv + gates + states (+ y split)
    conv_gate_kernel<<<dim3(CONV_DIM / 256, NTOK / TPER), 256>>>(convw, out + (size_t)NTOK * HIDDEN);

    // GEMM2: out = y @ w_out^T  [16384 x 2048]
    gemm_bf16x3<<<dim3(HIDDEN / BN, NTOK / BM), 256, GSMEM_TOTAL>>>(yh, yl, wouth, woutl, out, HIDDEN);
}